// round 12
// baseline (speedup 1.0000x reference)
#include <cuda_runtime.h>
#include <math.h>
#include <math_constants.h>

#ifndef CUDART_INF_F
#define CUDART_INF_F __int_as_float(0x7f800000)
#endif

// ---------------------------------------------------------------------------
// AdaptivePrecisionKVCache — R11: single persistent kernel.
//   Phase 1: per-block contiguous-chunk two-bin min/max reduce (R3 SEL form).
//   Software grid barrier (last block finalizes params inline).
//   Phase 2: dequant the SAME chunk in reverse order -> L2-hit reads, DRAM
//   writes only (__stcs evict-first).
// Grid 592 = 148 SMs x 4 with __launch_bounds__(256,4): all blocks co-resident
// by construction, so the spin barrier cannot deadlock.
// Barrier state: g_cnt returns to 0 each launch; g_release is monotone and
// sampled by every block BEFORE it arrives -> correct across graph replays.
// ---------------------------------------------------------------------------

#define THREADS 256
#define NBLOCKS 592              // 148 * 4
#define THRESH 0.01f

__device__ float4 g_partials[NBLOCKS];     // smin, smax, lmin, lmax
__device__ float4 g_ps;                    // smin, 15/sden, sden/15, svalid
__device__ float4 g_pl;                    // lmin, 255/lden, lden/255, lvalid
__device__ unsigned int g_cnt = 0;         // barrier arrivals (self-resetting)
__device__ unsigned int g_release = 0;     // barrier epoch (monotone)

struct MM { float smin, smax, lmin, lmax; };

__device__ __forceinline__ void mm_init(MM& m) {
    float inf = CUDART_INF_F;
    m.smin = inf; m.smax = -inf; m.lmin = inf; m.lmax = -inf;
}

// R3-proven branchless form: FSETP + 4 FSEL + 4 FMNMX (measured best).
__device__ __forceinline__ void acc_val(float x, MM& m) {
    bool big = fabsf(x) > THRESH;
    float inf = CUDART_INF_F;
    m.smin = fminf(m.smin, big ?  inf : x);
    m.smax = fmaxf(m.smax, big ? -inf : x);
    m.lmin = fminf(m.lmin, big ? x :  inf);
    m.lmax = fmaxf(m.lmax, big ? x : -inf);
}

__device__ __forceinline__ void acc_vec(float4 v, MM& m) {
    acc_val(v.x, m); acc_val(v.y, m); acc_val(v.z, m); acc_val(v.w, m);
}

__device__ __forceinline__ void mm_merge(MM& a, const MM& b) {
    a.smin = fminf(a.smin, b.smin);
    a.smax = fmaxf(a.smax, b.smax);
    a.lmin = fminf(a.lmin, b.lmin);
    a.lmax = fmaxf(a.lmax, b.lmax);
}

__device__ __forceinline__ void warp_reduce(MM& m) {
    #pragma unroll
    for (int o = 16; o > 0; o >>= 1) {
        m.smin = fminf(m.smin, __shfl_xor_sync(0xffffffffu, m.smin, o));
        m.smax = fmaxf(m.smax, __shfl_xor_sync(0xffffffffu, m.smax, o));
        m.lmin = fminf(m.lmin, __shfl_xor_sync(0xffffffffu, m.lmin, o));
        m.lmax = fmaxf(m.lmax, __shfl_xor_sync(0xffffffffu, m.lmax, o));
    }
}

__device__ __forceinline__ MM block_reduce(MM m) {
    __shared__ MM sm[THREADS / 32];
    warp_reduce(m);
    int w = threadIdx.x >> 5;
    if ((threadIdx.x & 31) == 0) sm[w] = m;
    __syncthreads();
    MM r = sm[0];
    if (threadIdx.x == 0) {
        #pragma unroll
        for (int i = 1; i < THREADS / 32; i++) mm_merge(r, sm[i]);
    }
    __syncthreads();   // protect sm for potential reuse
    return r;
}

__device__ __forceinline__ float dq(float x, float4 ps, float4 pl) {
    bool big = fabsf(x) > THRESH;
    float bmin = big ? pl.x : ps.x;
    float sc   = big ? pl.y : ps.y;
    float iv   = big ? pl.z : ps.z;
    float vd   = big ? pl.w : ps.w;
    float q = rintf((x - bmin) * sc);   // round-half-even == jnp.round
    float d = fmaf(q, iv, bmin);
    return (vd != 0.0f) ? d : x;
}

__device__ __forceinline__ float4 dq4(float4 v, float4 ps, float4 pl) {
    v.x = dq(v.x, ps, pl);
    v.y = dq(v.y, ps, pl);
    v.z = dq(v.z, ps, pl);
    v.w = dq(v.w, ps, pl);
    return v;
}

__global__ void __launch_bounds__(THREADS, 4)
k_fused(const float* __restrict__ in, float* __restrict__ out, int n) {
    const float4* __restrict__ in4 = (const float4*)in;
    float4* __restrict__ out4 = (float4*)out;
    int nvec = n >> 2;

    // Sample barrier epoch BEFORE any arrival can happen.
    __shared__ unsigned int rel0_sh;
    if (threadIdx.x == 0)
        rel0_sh = *(volatile unsigned int*)&g_release;
    __syncthreads();
    unsigned int rel0 = rel0_sh;

    // Contiguous chunk per block.
    int chunk = (nvec + NBLOCKS - 1) / NBLOCKS;
    int base = blockIdx.x * chunk;
    int end = base + chunk;
    if (end > nvec) end = nvec;

    // ---------------- Phase 1: reduce own chunk ----------------
    MM m0, m1, m2, m3;
    mm_init(m0); mm_init(m1); mm_init(m2); mm_init(m3);
    for (int i = base + threadIdx.x; i < end; i += 4 * THREADS) {
        int i1 = i + THREADS, i2 = i + 2 * THREADS, i3 = i + 3 * THREADS;
        float4 v0, v1, v2, v3;
        bool ok1 = i1 < end, ok2 = i2 < end, ok3 = i3 < end;
        v0 = in4[i];
        if (ok1) v1 = in4[i1];
        if (ok2) v2 = in4[i2];
        if (ok3) v3 = in4[i3];
        acc_vec(v0, m0);
        if (ok1) acc_vec(v1, m1);
        if (ok2) acc_vec(v2, m2);
        if (ok3) acc_vec(v3, m3);
    }
    // scalar tail (n not multiple of 4)
    if (blockIdx.x == 0) {
        for (int j = (nvec << 2) + threadIdx.x; j < n; j += blockDim.x)
            acc_val(in[j], m0);
    }
    mm_merge(m0, m1); mm_merge(m2, m3); mm_merge(m0, m2);
    MM r = block_reduce(m0);

    // ---------------- Grid barrier + inline finalize ----------------
    __shared__ bool amLast;
    if (threadIdx.x == 0) {
        g_partials[blockIdx.x] = make_float4(r.smin, r.smax, r.lmin, r.lmax);
        __threadfence();
        unsigned int old = atomicAdd(&g_cnt, 1u);
        amLast = (old == (unsigned int)(gridDim.x - 1));
    }
    __syncthreads();

    if (amLast) {
        MM m; mm_init(m);
        for (int k = threadIdx.x; k < NBLOCKS; k += blockDim.x) {
            float4 p = g_partials[k];
            m.smin = fminf(m.smin, p.x);
            m.smax = fmaxf(m.smax, p.y);
            m.lmin = fminf(m.lmin, p.z);
            m.lmax = fmaxf(m.lmax, p.w);
        }
        MM f = block_reduce(m);
        if (threadIdx.x == 0) {
            bool sv = f.smin < f.smax;
            float sd = sv ? (f.smax - f.smin) : 1.0f;
            g_ps = make_float4(f.smin, 15.0f / sd, sd / 15.0f, sv ? 1.0f : 0.0f);
            bool lv = f.lmin < f.lmax;
            float ld = lv ? (f.lmax - f.lmin) : 1.0f;
            g_pl = make_float4(f.lmin, 255.0f / ld, ld / 255.0f, lv ? 1.0f : 0.0f);
            g_cnt = 0;                    // reset BEFORE release -> replay-safe
            __threadfence();
            atomicAdd(&g_release, 1u);    // open the barrier
        }
    } else {
        if (threadIdx.x == 0) {
            while (*(volatile unsigned int*)&g_release == rel0)
                __nanosleep(64);
        }
    }
    __syncthreads();
    __threadfence();  // acquire: params visible before phase 2 reads

    // Params via L2 (bypass potentially-stale L1 path).
    float4 ps, pl;
    ps.x = __ldcg(&g_ps.x); ps.y = __ldcg(&g_ps.y);
    ps.z = __ldcg(&g_ps.z); ps.w = __ldcg(&g_ps.w);
    pl.x = __ldcg(&g_pl.x); pl.y = __ldcg(&g_pl.y);
    pl.z = __ldcg(&g_pl.z); pl.w = __ldcg(&g_pl.w);

    // ---------------- Phase 2: dequant own chunk, reverse order ----------------
    int len = end - base;
    int span = 4 * THREADS;
    int nsteps = (len + span - 1) / span;
    for (int s = nsteps - 1; s >= 0; --s) {
        int i = base + s * span + threadIdx.x;
        int i1 = i + THREADS, i2 = i + 2 * THREADS, i3 = i + 3 * THREADS;
        float4 v0, v1, v2, v3;
        bool ok0 = i < end, ok1 = i1 < end, ok2 = i2 < end, ok3 = i3 < end;
        if (ok0) v0 = in4[i];
        if (ok1) v1 = in4[i1];
        if (ok2) v2 = in4[i2];
        if (ok3) v3 = in4[i3];
        if (ok0) __stcs(&out4[i],  dq4(v0, ps, pl));
        if (ok1) __stcs(&out4[i1], dq4(v1, ps, pl));
        if (ok2) __stcs(&out4[i2], dq4(v2, ps, pl));
        if (ok3) __stcs(&out4[i3], dq4(v3, ps, pl));
    }
    if (blockIdx.x == 0) {
        for (int j = (nvec << 2) + threadIdx.x; j < n; j += blockDim.x)
            __stcs(&out[j], dq(in[j], ps, pl));
    }
}

extern "C" void kernel_launch(void* const* d_in, const int* in_sizes, int n_in,
                              void* d_out, int out_size) {
    (void)n_in; (void)out_size;
    const float* in = (const float*)d_in[0];
    float* out = (float*)d_out;
    int n = in_sizes[0];
    k_fused<<<NBLOCKS, THREADS>>>(in, out, n);
}

// round 13
// speedup vs baseline: 1.0659x; 1.0659x over previous
#include <cuda_runtime.h>
#include <math.h>
#include <math_constants.h>

#ifndef CUDART_INF_F
#define CUDART_INF_F __int_as_float(0x7f800000)
#endif

// ---------------------------------------------------------------------------
// AdaptivePrecisionKVCache — R12: best-known 3-kernel structure (R6) with
// write-through output stores.
//   small bin: |x| <= 0.01, levels = 15 ; large bin: |x| > 0.01, levels = 255
//   valid bin <=> bmin < bmax
// R12 delta vs R6:
//   - k_dequant stores via __stwt (st.global.wt): the 134MB output stream does
//     NOT allocate in L2, so the input lines left resident by k_reduce survive
//     and dequant's reversed-order reads hit L2 instead of DRAM.
// ---------------------------------------------------------------------------

#define THRESH 0.01f
#define RED_BLOCKS 2368          // 148 SMs * 16
#define RED_THREADS 256
#define DQ_THREADS 256
#define DQ_UNROLL 4

__device__ float4 g_partials[RED_BLOCKS];  // x=smin, y=smax, z=lmin, w=lmax
__device__ float4 g_ps;                    // smin, 15/sden, sden/15, svalid
__device__ float4 g_pl;                    // lmin, 255/lden, lden/255, lvalid

struct MM { float smin, smax, lmin, lmax; };

__device__ __forceinline__ void mm_init(MM& m) {
    float inf = CUDART_INF_F;
    m.smin = inf; m.smax = -inf; m.lmin = inf; m.lmax = -inf;
}

// R3-proven branchless form: FSETP + 4 FSEL + 4 FMNMX (measured best).
__device__ __forceinline__ void acc_val(float x, MM& m) {
    bool big = fabsf(x) > THRESH;
    float inf = CUDART_INF_F;
    m.smin = fminf(m.smin, big ?  inf : x);
    m.smax = fmaxf(m.smax, big ? -inf : x);
    m.lmin = fminf(m.lmin, big ? x :  inf);
    m.lmax = fmaxf(m.lmax, big ? x : -inf);
}

__device__ __forceinline__ void acc_vec(float4 v, MM& m) {
    acc_val(v.x, m); acc_val(v.y, m); acc_val(v.z, m); acc_val(v.w, m);
}

__device__ __forceinline__ void mm_merge(MM& a, const MM& b) {
    a.smin = fminf(a.smin, b.smin);
    a.smax = fmaxf(a.smax, b.smax);
    a.lmin = fminf(a.lmin, b.lmin);
    a.lmax = fmaxf(a.lmax, b.lmax);
}

__device__ __forceinline__ void warp_reduce(MM& m) {
    #pragma unroll
    for (int o = 16; o > 0; o >>= 1) {
        m.smin = fminf(m.smin, __shfl_xor_sync(0xffffffffu, m.smin, o));
        m.smax = fmaxf(m.smax, __shfl_xor_sync(0xffffffffu, m.smax, o));
        m.lmin = fminf(m.lmin, __shfl_xor_sync(0xffffffffu, m.lmin, o));
        m.lmax = fmaxf(m.lmax, __shfl_xor_sync(0xffffffffu, m.lmax, o));
    }
}

__device__ __forceinline__ MM block_reduce(MM m) {
    warp_reduce(m);
    __shared__ MM sm[RED_THREADS / 32];
    int w = threadIdx.x >> 5;
    if ((threadIdx.x & 31) == 0) sm[w] = m;
    __syncthreads();
    MM r = sm[0];
    if (threadIdx.x == 0) {
        #pragma unroll
        for (int i = 1; i < RED_THREADS / 32; i++) mm_merge(r, sm[i]);
    }
    return r;
}

__global__ void __launch_bounds__(RED_THREADS)
k_reduce(const float* __restrict__ in, int n) {
    MM m0, m1, m2, m3;
    mm_init(m0); mm_init(m1); mm_init(m2); mm_init(m3);
    int nvec = n >> 2;
    const float4* __restrict__ in4 = (const float4*)in;
    int S = gridDim.x * blockDim.x;
    int tid = blockIdx.x * blockDim.x + threadIdx.x;
    int i = tid;
    for (; i + 3 * S < nvec; i += 4 * S) {
        float4 v0 = in4[i];
        float4 v1 = in4[i + S];
        float4 v2 = in4[i + 2 * S];
        float4 v3 = in4[i + 3 * S];
        acc_vec(v0, m0); acc_vec(v1, m1); acc_vec(v2, m2); acc_vec(v3, m3);
    }
    for (; i < nvec; i += S) acc_vec(in4[i], m0);
    if (blockIdx.x == 0) {
        for (int j = (nvec << 2) + threadIdx.x; j < n; j += blockDim.x)
            acc_val(in[j], m0);
    }
    mm_merge(m0, m1); mm_merge(m2, m3); mm_merge(m0, m2);
    MM r = block_reduce(m0);
    if (threadIdx.x == 0)
        g_partials[blockIdx.x] = make_float4(r.smin, r.smax, r.lmin, r.lmax);
}

__global__ void __launch_bounds__(RED_THREADS)
k_finalize() {
    MM m; mm_init(m);
    for (int i = threadIdx.x; i < RED_BLOCKS; i += blockDim.x) {
        float4 p = g_partials[i];
        m.smin = fminf(m.smin, p.x);
        m.smax = fmaxf(m.smax, p.y);
        m.lmin = fminf(m.lmin, p.z);
        m.lmax = fmaxf(m.lmax, p.w);
    }
    MM f = block_reduce(m);
    if (threadIdx.x == 0) {
        bool sv = f.smin < f.smax;
        float sd = sv ? (f.smax - f.smin) : 1.0f;
        g_ps = make_float4(f.smin, 15.0f / sd, sd / 15.0f, sv ? 1.0f : 0.0f);
        bool lv = f.lmin < f.lmax;
        float ld = lv ? (f.lmax - f.lmin) : 1.0f;
        g_pl = make_float4(f.lmin, 255.0f / ld, ld / 255.0f, lv ? 1.0f : 0.0f);
    }
}

__device__ __forceinline__ float dq(float x, float4 ps, float4 pl) {
    bool big = fabsf(x) > THRESH;
    float bmin = big ? pl.x : ps.x;
    float sc   = big ? pl.y : ps.y;
    float iv   = big ? pl.z : ps.z;
    float vd   = big ? pl.w : ps.w;
    float q = rintf((x - bmin) * sc);   // rintf == round-half-even == jnp.round
    float d = fmaf(q, iv, bmin);
    return (vd != 0.0f) ? d : x;
}

__device__ __forceinline__ float4 dq4(float4 v, float4 ps, float4 pl) {
    v.x = dq(v.x, ps, pl);
    v.y = dq(v.y, ps, pl);
    v.z = dq(v.z, ps, pl);
    v.w = dq(v.w, ps, pl);
    return v;
}

// Reversed block order (start on the L2-hot tail) + write-through stores
// (no L2 allocation for the output stream).
__global__ void __launch_bounds__(DQ_THREADS)
k_dequant(const float* __restrict__ in, float* __restrict__ out, int n) {
    const float4 ps = g_ps;
    const float4 pl = g_pl;
    int nvec = n >> 2;
    const float4* __restrict__ in4 = (const float4*)in;
    float4* __restrict__ out4 = (float4*)out;
    int rb = gridDim.x - 1 - blockIdx.x;
    int base = rb * (DQ_UNROLL * DQ_THREADS) + threadIdx.x;

    int idx[DQ_UNROLL];
    float4 v[DQ_UNROLL];
    bool ok[DQ_UNROLL];
    #pragma unroll
    for (int u = 0; u < DQ_UNROLL; u++) {
        idx[u] = base + u * DQ_THREADS;
        ok[u] = idx[u] < nvec;
        if (ok[u]) v[u] = in4[idx[u]];
    }
    #pragma unroll
    for (int u = 0; u < DQ_UNROLL; u++) {
        if (ok[u]) __stwt(&out4[idx[u]], dq4(v[u], ps, pl));
    }
    if (blockIdx.x == 0) {
        for (int j = (nvec << 2) + threadIdx.x; j < n; j += blockDim.x)
            __stwt(&out[j], dq(in[j], ps, pl));
    }
}

extern "C" void kernel_launch(void* const* d_in, const int* in_sizes, int n_in,
                              void* d_out, int out_size) {
    (void)n_in; (void)out_size;
    const float* in = (const float*)d_in[0];
    float* out = (float*)d_out;
    int n = in_sizes[0];

    int nvec = n >> 2;

    k_reduce<<<RED_BLOCKS, RED_THREADS>>>(in, n);
    k_finalize<<<1, RED_THREADS>>>();

    int chunk = DQ_UNROLL * DQ_THREADS;
    int dq_blocks = (nvec + chunk - 1) / chunk;
    if (dq_blocks < 1) dq_blocks = 1;
    k_dequant<<<dq_blocks, DQ_THREADS>>>(in, out, n);
}